// round 10
// baseline (speedup 1.0000x reference)
#include <cuda_runtime.h>
#include <cuda_bf16.h>
#include <cstdint>

#define E_EXPERTS 8
#define H_DIM 2048
#define I_DIM 1024
#define T_TOK 16384

// ---------------- device scratch (allocation-free rule) ----------------
__device__ float a_r[(size_t)T_TOK * H_DIM];                  // rna-rounded activations
__device__ float u_scratch[(size_t)T_TOK * I_DIM];            // up-proj result
__device__ float h_scratch[(size_t)T_TOK * I_DIM];            // swiglu output (rounded)
__device__ float gate_r[(size_t)E_EXPERTS * H_DIM * I_DIM];   // rna-rounded weights [E][K][N]
__device__ float up_r[(size_t)E_EXPERTS * H_DIM * I_DIM];
__device__ float down_r[(size_t)E_EXPERTS * H_DIM * I_DIM];

// ---------------- helpers ----------------
__device__ __forceinline__ float rna_tf32(float x) {
    uint32_t o;
    asm("cvt.rna.tf32.f32 %0, %1;" : "=r"(o) : "f"(x));
    return __uint_as_float(o);
}
__device__ __forceinline__ uint32_t smem_u32(const void* p) {
    return (uint32_t)__cvta_generic_to_shared(p);
}
__device__ __forceinline__ void cp_async16(uint32_t dst, const void* src) {
    asm volatile("cp.async.cg.shared.global [%0], [%1], 16;" :: "r"(dst), "l"(src) : "memory");
}
__device__ __forceinline__ void ldsm_x4(uint32_t* r, uint32_t addr) {
    asm volatile("ldmatrix.sync.aligned.m8n8.x4.shared.b16 {%0,%1,%2,%3}, [%4];"
                 : "=r"(r[0]), "=r"(r[1]), "=r"(r[2]), "=r"(r[3]) : "r"(addr));
}
__device__ __forceinline__ void mma_tf32(float* d, const uint32_t* a, const uint32_t* b) {
    asm volatile(
        "mma.sync.aligned.m16n8k8.row.col.f32.tf32.tf32.f32 "
        "{%0,%1,%2,%3}, {%4,%5,%6,%7}, {%8,%9}, {%0,%1,%2,%3};"
        : "+f"(d[0]), "+f"(d[1]), "+f"(d[2]), "+f"(d[3])
        : "r"(a[0]), "r"(a[1]), "r"(a[2]), "r"(a[3]), "r"(b[0]), "r"(b[1]));
}

// ---------------- prepass: rna-round (elementwise) ----------------
__global__ void round_kernel(const float4* __restrict__ in, float4* __restrict__ out, int n4) {
    int i = blockIdx.x * blockDim.x + threadIdx.x;
    if (i < n4) {
        float4 v = in[i];
        v.x = rna_tf32(v.x); v.y = rna_tf32(v.y);
        v.z = rna_tf32(v.z); v.w = rna_tf32(v.w);
        out[i] = v;
    }
}

// -----------------------------------------------------------------------------
// Grouped GEMM via mma.sync tf32; all operands pre-rounded.
// NEW CONFIG: CTA 128x128 with 128 threads = 4 warps (2M x 2N), warp tile
// 64x64 (ma=4, na=8). Smem-read bytes/MAC drops 0.25 -> 0.183, raising the
// crossbar-imposed tensor ceiling from 50% to ~68%, while 2 CTA/SM is retained
// (acc 128 regs/thread x 128 threads fits RF for 2 CTAs) so CTA barriers
// interleave. BK=32, S=3 cp.async ring.
// EPI==1: epilogue loads u from aux, stores rna(silu(g)*u).
// -----------------------------------------------------------------------------
template <int EPI>
__global__ __launch_bounds__(128, 2)
void mma_gemm(const float* __restrict__ A, const float* __restrict__ B0,
              const float* __restrict__ aux, const int* __restrict__ gsz,
              float* __restrict__ C, int K, int N) {
    constexpr int BM = 128, BN = 128, BK = 32, S = 3;
    constexpr int APAD = 36;
    constexpr int BPAD = BN + 8;            // 136
    constexpr int A_FL = BM * APAD;         // 4608
    constexpr int B_FL = BK * BPAD;         // 4352
    constexpr int STAGE = A_FL + B_FL;      // 8960 floats

    extern __shared__ float sm[];
    __shared__ int bound[E_EXPERTS + 1];

    const int tid = threadIdx.x;
    const int wid = tid >> 5;
    const int lane = tid & 31;
    const int wm = wid & 1;                 // 2 warp-rows of 64
    const int wn = wid >> 1;                // 2 warp-cols of 64
    const int lr = lane >> 2;               // 0..7
    const int lc = lane & 3;                // 0..3

    // ldmatrix A lane-address
    const int gi = lane >> 3;
    const int gr = lane & 7;
    const int a_row = wm * 64 + ((gi & 1) << 3) + gr;
    const int a_col = (gi >> 1) << 2;

    if (tid == 0) {
        int acc = 0;
        bound[0] = 0;
        #pragma unroll
        for (int e = 0; e < E_EXPERTS; e++) { acc += gsz[e]; bound[e + 1] = acc; }
    }
    __syncthreads();

    const int m0 = blockIdx.y * BM;
    const int n0 = blockIdx.x * BN;
    const int nch = K / BK;
    const uint32_t sm_u = smem_u32(sm);

    int row = m0;
    while (row < m0 + BM) {
        int e = 0;
        while (bound[e + 1] <= row) e++;
        const int seg_end = bound[e + 1] < m0 + BM ? bound[e + 1] : m0 + BM;
        const float* Be = B0 + (size_t)e * K * N;

        float acc[4][8][4];                 // [ma][na][quad] = 128 regs
        #pragma unroll
        for (int ma = 0; ma < 4; ma++)
            #pragma unroll
            for (int na = 0; na < 8; na++)
                #pragma unroll
                for (int q = 0; q < 4; q++) acc[ma][na][q] = 0.f;

        auto load_stage = [&](int c) {
            int s = c % S;
            float* as = sm + s * STAGE;
            int kc = c * BK;
            // A tile: 128x32 = 1024 float4, 8 per thread
            #pragma unroll
            for (int i = 0; i < 8; i++) {
                int idx = tid + i * 128;
                int m = idx >> 3, kq = (idx & 7) << 2;
                cp_async16(smem_u32(as + m * APAD + kq),
                           A + (size_t)(m0 + m) * K + kc + kq);
            }
            // B tile: 32x128 = 1024 float4, 8 per thread
            float* bs = as + A_FL;
            #pragma unroll
            for (int i = 0; i < 8; i++) {
                int idx = tid + i * 128;
                int kr = idx >> 5, nq = (idx & 31) << 2;
                cp_async16(smem_u32(bs + kr * BPAD + nq),
                           Be + (size_t)(kc + kr) * N + n0 + nq);
            }
            asm volatile("cp.async.commit_group;" ::: "memory");
        };

        #pragma unroll
        for (int c = 0; c < S - 1; c++) load_stage(c);

        for (int c = 0; c < nch; c++) {
            asm volatile("cp.async.wait_group %0;" :: "n"(S - 2));
            __syncthreads();
            if (c + S - 1 < nch) load_stage(c + S - 1);
            else asm volatile("cp.async.commit_group;" ::: "memory");

            const uint32_t as_u = sm_u + (uint32_t)((c % S) * STAGE) * 4u;
            const float* bs = sm + (c % S) * STAGE + A_FL;
            const uint32_t aA = as_u + (uint32_t)(a_row * APAD + a_col) * 4u;
            const int cbase = wn * 64 + lr;

            #pragma unroll
            for (int ks = 0; ks < 4; ks++) {
                const int k0 = ks * 8;
                uint32_t af[4][4];
                #pragma unroll
                for (int ma = 0; ma < 4; ma++)
                    ldsm_x4(af[ma], aA + (uint32_t)(ma * 16 * APAD + k0) * 4u);
                uint32_t bf[8][2];
                #pragma unroll
                for (int na = 0; na < 8; na++) {
                    int cb = cbase + na * 8;
                    bf[na][0] = __float_as_uint(bs[(size_t)(k0 + lc) * BPAD + cb]);
                    bf[na][1] = __float_as_uint(bs[(size_t)(k0 + lc + 4) * BPAD + cb]);
                }
                #pragma unroll
                for (int na = 0; na < 8; na++)
                    #pragma unroll
                    for (int ma = 0; ma < 4; ma++)
                        mma_tf32(acc[ma][na], af[ma], bf[na]);
            }
        }

        // ---------------- epilogue ----------------
        #pragma unroll
        for (int ma = 0; ma < 4; ma++) {
            int r1 = m0 + wm * 64 + ma * 16 + lr;
            int r2 = r1 + 8;
            bool a1 = (r1 >= row && r1 < seg_end);
            bool a2 = (r2 >= row && r2 < seg_end);
            #pragma unroll
            for (int na = 0; na < 8; na++) {
                int col = n0 + wn * 64 + na * 8 + 2 * lc;
                if (EPI == 1) {
                    if (a1) {
                        float2 uv = *(const float2*)(aux + (size_t)r1 * N + col);
                        float g0 = acc[ma][na][0], g1 = acc[ma][na][1];
                        float2 o;
                        o.x = rna_tf32(g0 / (1.f + __expf(-g0)) * uv.x);
                        o.y = rna_tf32(g1 / (1.f + __expf(-g1)) * uv.y);
                        *(float2*)(C + (size_t)r1 * N + col) = o;
                    }
                    if (a2) {
                        float2 uv = *(const float2*)(aux + (size_t)r2 * N + col);
                        float g2 = acc[ma][na][2], g3 = acc[ma][na][3];
                        float2 o;
                        o.x = rna_tf32(g2 / (1.f + __expf(-g2)) * uv.x);
                        o.y = rna_tf32(g3 / (1.f + __expf(-g3)) * uv.y);
                        *(float2*)(C + (size_t)r2 * N + col) = o;
                    }
                } else {
                    if (a1)
                        *(float2*)(C + (size_t)r1 * N + col) =
                            make_float2(acc[ma][na][0], acc[ma][na][1]);
                    if (a2)
                        *(float2*)(C + (size_t)r2 * N + col) =
                            make_float2(acc[ma][na][2], acc[ma][na][3]);
                }
            }
        }
        __syncthreads();   // protect smem ring across segments / tail cp.asyncs
        row = seg_end;
    }
}

// ---------------- launch ----------------
extern "C" void kernel_launch(void* const* d_in, const int* in_sizes, int n_in,
                              void* d_out, int out_size) {
    (void)in_sizes; (void)n_in; (void)out_size;
    const float* hidden = (const float*)d_in[0];
    const float* gate_w = (const float*)d_in[1];
    const float* up_w   = (const float*)d_in[2];
    const float* down_w = (const float*)d_in[3];
    const int*   gs     = (const int*)d_in[4];
    float* out = (float*)d_out;

    float *aP, *uP, *hP, *gP, *upP, *dP;
    cudaGetSymbolAddress((void**)&aP, a_r);
    cudaGetSymbolAddress((void**)&uP, u_scratch);
    cudaGetSymbolAddress((void**)&hP, h_scratch);
    cudaGetSymbolAddress((void**)&gP, gate_r);
    cudaGetSymbolAddress((void**)&upP, up_r);
    cudaGetSymbolAddress((void**)&dP, down_r);

    constexpr int SMEM = 3 * (4608 + 4352) * 4;   // 107,520 B -> 2 CTA/SM
    cudaFuncSetAttribute((const void*)mma_gemm<0>,
                         cudaFuncAttributeMaxDynamicSharedMemorySize, SMEM);
    cudaFuncSetAttribute((const void*)mma_gemm<1>,
                         cudaFuncAttributeMaxDynamicSharedMemorySize, SMEM);

    // prepass: rna-round activations and all weights (no cvt in mainloops)
    int nA4 = (int)((size_t)T_TOK * H_DIM / 4);
    int nW4 = (int)((size_t)E_EXPERTS * H_DIM * I_DIM / 4);
    round_kernel<<<(nA4 + 255) / 256, 256>>>((const float4*)hidden, (float4*)aP, nA4);
    round_kernel<<<(nW4 + 255) / 256, 256>>>((const float4*)gate_w, (float4*)gP, nW4);
    round_kernel<<<(nW4 + 255) / 256, 256>>>((const float4*)up_w,   (float4*)upP, nW4);
    round_kernel<<<(nW4 + 255) / 256, 256>>>((const float4*)down_w, (float4*)dP, nW4);

    // 1) up-projection: u = a @ up_w              (A=[T,H], B=[H,I])
    mma_gemm<0><<<dim3(I_DIM / 128, T_TOK / 128), 128, SMEM>>>(
        aP, upP, nullptr, gs, uP, H_DIM, I_DIM);
    // 2) gate + SwiGLU: h = rna(silu(a @ gate_w) * u)
    mma_gemm<1><<<dim3(I_DIM / 128, T_TOK / 128), 128, SMEM>>>(
        aP, gP, uP, gs, hP, H_DIM, I_DIM);
    // 3) down-projection: out = h @ down_w        (A=[T,I], B=[I,H])
    mma_gemm<0><<<dim3(H_DIM / 128, T_TOK / 128), 128, SMEM>>>(
        hP, dP, nullptr, gs, out, I_DIM, H_DIM);
}

// round 11
// speedup vs baseline: 1.9679x; 1.9679x over previous
#include <cuda_runtime.h>
#include <cuda_fp16.h>
#include <cstdint>

#define E_EXPERTS 8
#define H_DIM 2048
#define I_DIM 1024
#define T_TOK 16384

// ---------------- device scratch (allocation-free rule) ----------------
__device__ __half a_h[(size_t)T_TOK * H_DIM];                  // fp16 activations
__device__ __half u_s[(size_t)T_TOK * I_DIM];                  // up-proj result (fp16)
__device__ __half h_s[(size_t)T_TOK * I_DIM];                  // swiglu output (fp16)
__device__ __half gate_h[(size_t)E_EXPERTS * H_DIM * I_DIM];   // fp16 weights [E][K][N]
__device__ __half up_h[(size_t)E_EXPERTS * H_DIM * I_DIM];
__device__ __half down_h[(size_t)E_EXPERTS * H_DIM * I_DIM];

// ---------------- helpers ----------------
__device__ __forceinline__ uint32_t smem_u32(const void* p) {
    return (uint32_t)__cvta_generic_to_shared(p);
}
__device__ __forceinline__ void cp_async16(uint32_t dst, const void* src) {
    asm volatile("cp.async.cg.shared.global [%0], [%1], 16;" :: "r"(dst), "l"(src) : "memory");
}
__device__ __forceinline__ void ldsm_x4(uint32_t* r, uint32_t addr) {
    asm volatile("ldmatrix.sync.aligned.m8n8.x4.shared.b16 {%0,%1,%2,%3}, [%4];"
                 : "=r"(r[0]), "=r"(r[1]), "=r"(r[2]), "=r"(r[3]) : "r"(addr));
}
__device__ __forceinline__ void ldsm_x4_t(uint32_t* r, uint32_t addr) {
    asm volatile("ldmatrix.sync.aligned.m8n8.x4.trans.shared.b16 {%0,%1,%2,%3}, [%4];"
                 : "=r"(r[0]), "=r"(r[1]), "=r"(r[2]), "=r"(r[3]) : "r"(addr));
}
__device__ __forceinline__ void mma_f16(float* d, const uint32_t* a, const uint32_t* b) {
    asm volatile(
        "mma.sync.aligned.m16n8k16.row.col.f32.f16.f16.f32 "
        "{%0,%1,%2,%3}, {%4,%5,%6,%7}, {%8,%9}, {%0,%1,%2,%3};"
        : "+f"(d[0]), "+f"(d[1]), "+f"(d[2]), "+f"(d[3])
        : "r"(a[0]), "r"(a[1]), "r"(a[2]), "r"(a[3]), "r"(b[0]), "r"(b[1]));
}

// ---------------- prepass: fp32 -> fp16 (RN) ----------------
__global__ void f2h_kernel(const float4* __restrict__ in, uint2* __restrict__ out, int n4) {
    int i = blockIdx.x * blockDim.x + threadIdx.x;
    if (i < n4) {
        float4 v = in[i];
        __half2 h0 = __floats2half2_rn(v.x, v.y);
        __half2 h1 = __floats2half2_rn(v.z, v.w);
        uint2 o;
        o.x = *(uint32_t*)&h0;
        o.y = *(uint32_t*)&h1;
        out[i] = o;
    }
}

// -----------------------------------------------------------------------------
// Grouped GEMM via mma.sync fp16 (m16n8k16, f32 accum) — 2x the MAC rate of the
// legacy tf32 path that rounds 6-10 showed to be instruction-rate saturated.
// C[m,n] = sum_k A[m,k] * B[expert(m)][k,n], all operands fp16 (11-bit
// significand == tf32, so rel_err is preserved).
// CTA 128x128, 256 threads = 8 warps (2M x 4N), warp tile 64x32, BK=32, S=3,
// 2 CTA/SM. A frags: ldmatrix.x4 on [m][k] tile; B frags: ldmatrix.x4.trans
// on [k][n] tile. APAD=40/BPAD=136 halves -> conflict-free LDSM phases.
// MODE 0: C fp16 raw. MODE 1: C fp16 = rn(silu(acc)*u) with u=aux fp16.
// MODE 2: C fp32 raw (final output).
// -----------------------------------------------------------------------------
template <int MODE>
__global__ __launch_bounds__(256, 2)
void mma_gemm(const __half* __restrict__ A, const __half* __restrict__ B0,
              const __half* __restrict__ aux, const int* __restrict__ gsz,
              void* __restrict__ Cv, int K, int N) {
    constexpr int BM = 128, BN = 128, BK = 32, S = 3;
    constexpr int APAD = 40;                 // halves (80B rows)
    constexpr int BPAD = BN + 8;             // 136 halves (272B rows)
    constexpr int A_HL = BM * APAD;          // 5120 halves
    constexpr int B_HL = BK * BPAD;          // 4352 halves
    constexpr int STAGE = A_HL + B_HL;       // 9472 halves = 18944 B

    extern __shared__ __half smh[];
    __shared__ int bound[E_EXPERTS + 1];

    const int tid = threadIdx.x;
    const int wid = tid >> 5;
    const int lane = tid & 31;
    const int wm = wid & 1;                  // 2 warp-rows of 64
    const int wn = wid >> 1;                 // 4 warp-cols of 32
    const int lr = lane >> 2;                // 0..7
    const int lc = lane & 3;                 // 0..3

    // ldmatrix lane addressing: row = (lane&15), col-half-offset = (lane>>4)*8
    const int l16 = lane & 15;
    const int lh8 = (lane >> 4) << 3;

    if (tid == 0) {
        int acc = 0;
        bound[0] = 0;
        #pragma unroll
        for (int e = 0; e < E_EXPERTS; e++) { acc += gsz[e]; bound[e + 1] = acc; }
    }
    __syncthreads();

    const int m0 = blockIdx.y * BM;
    const int n0 = blockIdx.x * BN;
    const int nch = K / BK;
    const uint32_t sm_u = smem_u32(smh);

    int row = m0;
    while (row < m0 + BM) {
        int e = 0;
        while (bound[e + 1] <= row) e++;
        const int seg_end = bound[e + 1] < m0 + BM ? bound[e + 1] : m0 + BM;
        const __half* Be = B0 + (size_t)e * K * N;

        float acc[4][4][4];                  // [ma][na][quad] = 64 regs
        #pragma unroll
        for (int ma = 0; ma < 4; ma++)
            #pragma unroll
            for (int na = 0; na < 4; na++)
                #pragma unroll
                for (int q = 0; q < 4; q++) acc[ma][na][q] = 0.f;

        auto load_stage = [&](int c) {
            int s = c % S;
            __half* as = smh + s * STAGE;
            int kc = c * BK;
            // A tile: 128 rows x 32 halves (64B/row) = 512 x 16B, 2/thread
            #pragma unroll
            for (int i = 0; i < 2; i++) {
                int idx = tid + i * 256;
                int m = idx >> 2, cc = (idx & 3) << 3;   // 8-half chunks
                cp_async16(smem_u32(as + m * APAD + cc),
                           A + (size_t)(m0 + m) * K + kc + cc);
            }
            // B tile: 32 rows x 128 halves (256B/row) = 512 x 16B, 2/thread
            __half* bs = as + A_HL;
            #pragma unroll
            for (int i = 0; i < 2; i++) {
                int idx = tid + i * 256;
                int kr = idx >> 4, nc = (idx & 15) << 3;
                cp_async16(smem_u32(bs + kr * BPAD + nc),
                           Be + (size_t)(kc + kr) * N + n0 + nc);
            }
            asm volatile("cp.async.commit_group;" ::: "memory");
        };

        #pragma unroll
        for (int c = 0; c < S - 1; c++) load_stage(c);

        for (int c = 0; c < nch; c++) {
            asm volatile("cp.async.wait_group %0;" :: "n"(S - 2));
            __syncthreads();
            if (c + S - 1 < nch) load_stage(c + S - 1);
            else asm volatile("cp.async.commit_group;" ::: "memory");

            const uint32_t as_u = sm_u + (uint32_t)((c % S) * STAGE) * 2u;
            const uint32_t bs_u = as_u + (uint32_t)A_HL * 2u;
            // A base: row = wm*64 + l16, col = lh8
            const uint32_t aA = as_u + (uint32_t)((wm * 64 + l16) * APAD + lh8) * 2u;
            // B base: krow = l16, col = wn*32 + lh8
            const uint32_t bB = bs_u + (uint32_t)(l16 * BPAD + wn * 32 + lh8) * 2u;

            #pragma unroll
            for (int ks = 0; ks < 2; ks++) {          // two K=16 slabs
                const int k0 = ks * 16;
                uint32_t af[4][4];
                #pragma unroll
                for (int ma = 0; ma < 4; ma++)
                    ldsm_x4(af[ma], aA + (uint32_t)(ma * 16 * APAD + k0) * 2u);
                uint32_t bq[2][4];                    // [na-pair][4 regs]
                #pragma unroll
                for (int g = 0; g < 2; g++)
                    ldsm_x4_t(bq[g], bB + (uint32_t)(k0 * BPAD + g * 16) * 2u);
                #pragma unroll
                for (int na = 0; na < 4; na++) {
                    const uint32_t* bf = &bq[na >> 1][(na & 1) << 1];
                    #pragma unroll
                    for (int ma = 0; ma < 4; ma++)
                        mma_f16(acc[ma][na], af[ma], bf);
                }
            }
        }

        // ---------------- epilogue ----------------
        #pragma unroll
        for (int ma = 0; ma < 4; ma++) {
            int r1 = m0 + wm * 64 + ma * 16 + lr;
            int r2 = r1 + 8;
            bool a1 = (r1 >= row && r1 < seg_end);
            bool a2 = (r2 >= row && r2 < seg_end);
            #pragma unroll
            for (int na = 0; na < 4; na++) {
                int col = n0 + wn * 32 + na * 8 + 2 * lc;
                float g0 = acc[ma][na][0], g1 = acc[ma][na][1];
                float g2 = acc[ma][na][2], g3 = acc[ma][na][3];
                if (MODE == 0) {
                    __half* C = (__half*)Cv;
                    if (a1) *(__half2*)(C + (size_t)r1 * N + col) = __floats2half2_rn(g0, g1);
                    if (a2) *(__half2*)(C + (size_t)r2 * N + col) = __floats2half2_rn(g2, g3);
                } else if (MODE == 1) {
                    __half* C = (__half*)Cv;
                    if (a1) {
                        float2 uv = __half22float2(*(const __half2*)(aux + (size_t)r1 * N + col));
                        float h0 = g0 / (1.f + __expf(-g0)) * uv.x;
                        float h1 = g1 / (1.f + __expf(-g1)) * uv.y;
                        *(__half2*)(C + (size_t)r1 * N + col) = __floats2half2_rn(h0, h1);
                    }
                    if (a2) {
                        float2 uv = __half22float2(*(const __half2*)(aux + (size_t)r2 * N + col));
                        float h2 = g2 / (1.f + __expf(-g2)) * uv.x;
                        float h3 = g3 / (1.f + __expf(-g3)) * uv.y;
                        *(__half2*)(C + (size_t)r2 * N + col) = __floats2half2_rn(h2, h3);
                    }
                } else {
                    float* C = (float*)Cv;
                    if (a1) *(float2*)(C + (size_t)r1 * N + col) = make_float2(g0, g1);
                    if (a2) *(float2*)(C + (size_t)r2 * N + col) = make_float2(g2, g3);
                }
            }
        }
        __syncthreads();   // protect smem ring across segments / tail cp.asyncs
        row = seg_end;
    }
}

// ---------------- launch ----------------
extern "C" void kernel_launch(void* const* d_in, const int* in_sizes, int n_in,
                              void* d_out, int out_size) {
    (void)in_sizes; (void)n_in; (void)out_size;
    const float* hidden = (const float*)d_in[0];
    const float* gate_w = (const float*)d_in[1];
    const float* up_w   = (const float*)d_in[2];
    const float* down_w = (const float*)d_in[3];
    const int*   gs     = (const int*)d_in[4];
    float* out = (float*)d_out;

    __half *aP, *uP, *hP, *gP, *upP, *dP;
    cudaGetSymbolAddress((void**)&aP, a_h);
    cudaGetSymbolAddress((void**)&uP, u_s);
    cudaGetSymbolAddress((void**)&hP, h_s);
    cudaGetSymbolAddress((void**)&gP, gate_h);
    cudaGetSymbolAddress((void**)&upP, up_h);
    cudaGetSymbolAddress((void**)&dP, down_h);

    constexpr int SMEM = 3 * (5120 + 4352) * 2;   // 56,832 B -> 2 CTA/SM
    cudaFuncSetAttribute((const void*)mma_gemm<0>,
                         cudaFuncAttributeMaxDynamicSharedMemorySize, SMEM);
    cudaFuncSetAttribute((const void*)mma_gemm<1>,
                         cudaFuncAttributeMaxDynamicSharedMemorySize, SMEM);
    cudaFuncSetAttribute((const void*)mma_gemm<2>,
                         cudaFuncAttributeMaxDynamicSharedMemorySize, SMEM);

    // prepass: fp32 -> fp16 for activations and all weights
    int nA4 = (int)((size_t)T_TOK * H_DIM / 4);
    int nW4 = (int)((size_t)E_EXPERTS * H_DIM * I_DIM / 4);
    f2h_kernel<<<(nA4 + 255) / 256, 256>>>((const float4*)hidden, (uint2*)aP, nA4);
    f2h_kernel<<<(nW4 + 255) / 256, 256>>>((const float4*)gate_w, (uint2*)gP, nW4);
    f2h_kernel<<<(nW4 + 255) / 256, 256>>>((const float4*)up_w,   (uint2*)upP, nW4);
    f2h_kernel<<<(nW4 + 255) / 256, 256>>>((const float4*)down_w, (uint2*)dP, nW4);

    // 1) up-projection: u = a @ up_w              (A=[T,H], B=[H,I])
    mma_gemm<0><<<dim3(I_DIM / 128, T_TOK / 128), 256, SMEM>>>(
        aP, upP, nullptr, gs, uP, H_DIM, I_DIM);
    // 2) gate + SwiGLU: h = rn16(silu(a @ gate_w) * u)
    mma_gemm<1><<<dim3(I_DIM / 128, T_TOK / 128), 256, SMEM>>>(
        aP, gP, uP, gs, hP, H_DIM, I_DIM);
    // 3) down-projection: out = h @ down_w        (A=[T,I], B=[I,H], fp32 out)
    mma_gemm<2><<<dim3(H_DIM / 128, T_TOK / 128), 256, SMEM>>>(
        hP, dP, nullptr, gs, out, I_DIM, H_DIM);
}